// round 1
// baseline (speedup 1.0000x reference)
#include <cuda_runtime.h>
#include <math.h>

#define N_NODES 50000
#define H 256
#define E_EDGES 800000
#define EPS_LN 1e-5f
#define EPS_BN 1e-5f

// ---------------- scratch (device globals; no allocation allowed) -------------
__device__ float g_x[(size_t)N_NODES * H];    // current node features
__device__ float g_xw[(size_t)N_NODES * H];   // x @ W
__device__ int   g_deg[N_NODES];
__device__ float g_dinv[N_NODES];
__device__ int   g_off[N_NODES + 1];
__device__ int   g_cur[N_NODES];
__device__ int   g_csrc[E_EDGES];
__device__ float g_sum[H];
__device__ float g_sumsq[H];
__device__ float g_scale[H];
__device__ float g_shift[H];

// ---------------- degree / CSR build ----------------
__global__ void k_zero_deg() {
    int i = blockIdx.x * blockDim.x + threadIdx.x;
    if (i < N_NODES) g_deg[i] = 0;
}

__global__ void k_count(const int* __restrict__ dst) {
    int e = blockIdx.x * blockDim.x + threadIdx.x;
    if (e < E_EDGES) atomicAdd(&g_deg[dst[e]], 1);
}

// single-block exclusive scan over degrees; also computes dinv and cursors
__global__ void k_scan() {
    __shared__ int swarp[32];
    __shared__ int s_carry;
    int tid = threadIdx.x, lane = tid & 31, wid = tid >> 5;
    if (tid == 0) s_carry = 0;
    __syncthreads();
    for (int base = 0; base < N_NODES; base += 1024) {
        int i = base + tid;
        int v = (i < N_NODES) ? g_deg[i] : 0;
        int x = v;
        #pragma unroll
        for (int o = 1; o < 32; o <<= 1) {
            int t = __shfl_up_sync(0xffffffffu, x, o);
            if (lane >= o) x += t;
        }
        if (lane == 31) swarp[wid] = x;
        __syncthreads();
        if (wid == 0) {
            int y = swarp[lane];
            #pragma unroll
            for (int o = 1; o < 32; o <<= 1) {
                int t = __shfl_up_sync(0xffffffffu, y, o);
                if (lane >= o) y += t;
            }
            swarp[lane] = y;
        }
        __syncthreads();
        int incl = x + (wid ? swarp[wid - 1] : 0);
        int carry = s_carry;
        if (i < N_NODES) {
            int o = carry + incl - v;
            g_off[i] = o;
            g_cur[i] = o;
            g_dinv[i] = rsqrtf((float)v + 1.0f);   // deg includes self-loop
        }
        __syncthreads();
        if (tid == 1023) s_carry = carry + incl;
        __syncthreads();
    }
    if (threadIdx.x == 0) g_off[N_NODES] = s_carry;
}

__global__ void k_fill(const int* __restrict__ src, const int* __restrict__ dst) {
    int e = blockIdx.x * blockDim.x + threadIdx.x;
    if (e < E_EDGES) {
        int d = dst[e];
        int pos = atomicAdd(&g_cur[d], 1);
        g_csrc[pos] = src[e];
    }
}

// ---------------- input proj + LayerNorm + ELU ----------------
__global__ void k_input(const float* __restrict__ ctrl,
                        const float* __restrict__ w_in, const float* __restrict__ b_in,
                        const float* __restrict__ ln_g, const float* __restrict__ ln_b) {
    int gwarp = (blockIdx.x * blockDim.x + threadIdx.x) >> 5;
    int lane = threadIdx.x & 31;
    if (gwarp >= N_NODES) return;
    float c = ctrl[gwarp];
    float v[8];
    float s = 0.f, s2 = 0.f;
    #pragma unroll
    for (int j = 0; j < 8; j++) {
        int ch = lane + 32 * j;
        float t = fmaf(c, w_in[ch], b_in[ch]);
        v[j] = t; s += t; s2 += t * t;
    }
    #pragma unroll
    for (int o = 16; o; o >>= 1) {
        s  += __shfl_xor_sync(0xffffffffu, s, o);
        s2 += __shfl_xor_sync(0xffffffffu, s2, o);
    }
    float mu = s * (1.0f / H);
    float var = fmaxf(s2 * (1.0f / H) - mu * mu, 0.f);
    float r = rsqrtf(var + EPS_LN);
    float* out = g_x + (size_t)gwarp * H;
    #pragma unroll
    for (int j = 0; j < 8; j++) {
        int ch = lane + 32 * j;
        float y = fmaf((v[j] - mu) * r, ln_g[ch], ln_b[ch]);
        y = (y > 0.f) ? y : expm1f(y);
        out[ch] = y;
    }
}

// ---------------- SGEMM: g_xw = g_x @ W   (bias dropped: cancels in BN) -------
#define BM 128
#define BN 128
#define BK 16
__global__ __launch_bounds__(256) void k_gemm(const float* __restrict__ W) {
    __shared__ float As[BK][BM];
    __shared__ float Bs[BK][BN];
    int tid = threadIdx.x;
    int bm = blockIdx.y * BM;
    int bn = blockIdx.x * BN;
    int tx = tid & 15, ty = tid >> 4;
    float acc[8][8];
    #pragma unroll
    for (int i = 0; i < 8; i++)
        #pragma unroll
        for (int j = 0; j < 8; j++) acc[i][j] = 0.f;

    for (int k0 = 0; k0 < H; k0 += BK) {
        #pragma unroll
        for (int r = 0; r < 2; r++) {
            int idx = tid + r * 256;
            // A tile: 128 rows x 16 k
            int arow = idx >> 2;
            int k4 = (idx & 3) * 4;
            int grow = bm + arow;
            float4 av = make_float4(0.f, 0.f, 0.f, 0.f);
            if (grow < N_NODES)
                av = *(const float4*)(g_x + (size_t)grow * H + k0 + k4);
            As[k4 + 0][arow] = av.x;
            As[k4 + 1][arow] = av.y;
            As[k4 + 2][arow] = av.z;
            As[k4 + 3][arow] = av.w;
            // B tile: 16 k x 128 cols
            int brow = idx >> 5;
            int bcol = (idx & 31) * 4;
            *(float4*)&Bs[brow][bcol] =
                *(const float4*)(W + (size_t)(k0 + brow) * H + bn + bcol);
        }
        __syncthreads();
        #pragma unroll
        for (int kk = 0; kk < BK; kk++) {
            float a[8], b[8];
            *(float4*)(a)     = *(float4*)&As[kk][ty * 8];
            *(float4*)(a + 4) = *(float4*)&As[kk][ty * 8 + 4];
            *(float4*)(b)     = *(float4*)&Bs[kk][tx * 8];
            *(float4*)(b + 4) = *(float4*)&Bs[kk][tx * 8 + 4];
            #pragma unroll
            for (int i = 0; i < 8; i++)
                #pragma unroll
                for (int j = 0; j < 8; j++)
                    acc[i][j] = fmaf(a[i], b[j], acc[i][j]);
        }
        __syncthreads();
    }
    #pragma unroll
    for (int i = 0; i < 8; i++) {
        int grow = bm + ty * 8 + i;
        if (grow < N_NODES) {
            float4* p = (float4*)(g_xw + (size_t)grow * H + bn + tx * 8);
            p[0] = *(float4*)&acc[i][0];
            p[1] = *(float4*)&acc[i][4];
        }
    }
}

// ---------------- zero BN accumulators ----------------
__global__ void k_zero_stats() {
    int t = threadIdx.x;
    g_sum[t] = 0.f;
    g_sumsq[t] = 0.f;
}

// ---------------- CSR aggregation + fused BN partial stats -------------------
// warp per node: agg = xw[node]*dinv^2 + sum_{e: dst==node} xw[src]*dinv[src]*dinv[node]
__global__ __launch_bounds__(256) void k_aggregate() {
    __shared__ float s_sum[H];
    __shared__ float s_sq[H];
    int tid = threadIdx.x;
    s_sum[tid] = 0.f;
    s_sq[tid] = 0.f;
    __syncthreads();

    int node = blockIdx.x * 8 + (tid >> 5);
    int lane = tid & 31;

    float dn = g_dinv[node];
    const float4* row = (const float4*)(g_xw + (size_t)node * H);
    float4 a0 = row[lane];
    float4 a1 = row[32 + lane];
    float w = dn * dn;
    float4 acc0 = make_float4(a0.x * w, a0.y * w, a0.z * w, a0.w * w);
    float4 acc1 = make_float4(a1.x * w, a1.y * w, a1.z * w, a1.w * w);

    int beg = g_off[node], end = g_off[node + 1];
    for (int j = beg; j < end; j++) {
        int s = g_csrc[j];
        float coef = g_dinv[s] * dn;
        const float4* r2 = (const float4*)(g_xw + (size_t)s * H);
        float4 b0 = r2[lane];
        float4 b1 = r2[32 + lane];
        acc0.x = fmaf(coef, b0.x, acc0.x);
        acc0.y = fmaf(coef, b0.y, acc0.y);
        acc0.z = fmaf(coef, b0.z, acc0.z);
        acc0.w = fmaf(coef, b0.w, acc0.w);
        acc1.x = fmaf(coef, b1.x, acc1.x);
        acc1.y = fmaf(coef, b1.y, acc1.y);
        acc1.z = fmaf(coef, b1.z, acc1.z);
        acc1.w = fmaf(coef, b1.w, acc1.w);
    }
    float4* out = (float4*)(g_x + (size_t)node * H);
    out[lane] = acc0;
    out[32 + lane] = acc1;

    int c0 = lane * 4, c1 = 128 + lane * 4;
    atomicAdd(&s_sum[c0 + 0], acc0.x); atomicAdd(&s_sq[c0 + 0], acc0.x * acc0.x);
    atomicAdd(&s_sum[c0 + 1], acc0.y); atomicAdd(&s_sq[c0 + 1], acc0.y * acc0.y);
    atomicAdd(&s_sum[c0 + 2], acc0.z); atomicAdd(&s_sq[c0 + 2], acc0.z * acc0.z);
    atomicAdd(&s_sum[c0 + 3], acc0.w); atomicAdd(&s_sq[c0 + 3], acc0.w * acc0.w);
    atomicAdd(&s_sum[c1 + 0], acc1.x); atomicAdd(&s_sq[c1 + 0], acc1.x * acc1.x);
    atomicAdd(&s_sum[c1 + 1], acc1.y); atomicAdd(&s_sq[c1 + 1], acc1.y * acc1.y);
    atomicAdd(&s_sum[c1 + 2], acc1.z); atomicAdd(&s_sq[c1 + 2], acc1.z * acc1.z);
    atomicAdd(&s_sum[c1 + 3], acc1.w); atomicAdd(&s_sq[c1 + 3], acc1.w * acc1.w);

    __syncthreads();
    atomicAdd(&g_sum[tid], s_sum[tid]);
    atomicAdd(&g_sumsq[tid], s_sq[tid]);
}

// ---------------- BN finalize: scale/shift ----------------
__global__ void k_bn_finalize(const float* __restrict__ gamma,
                              const float* __restrict__ beta) {
    int t = threadIdx.x;
    float mean = g_sum[t] * (1.0f / N_NODES);
    float var = fmaxf(g_sumsq[t] * (1.0f / N_NODES) - mean * mean, 0.f);
    float r = rsqrtf(var + EPS_BN);
    float sc = r * gamma[t];
    g_scale[t] = sc;
    g_shift[t] = beta[t] - mean * sc;
}

// ---------------- BN apply + ELU (in place on g_x) ----------------
__global__ void k_apply() {
    int i4 = blockIdx.x * blockDim.x + threadIdx.x;   // float4 index
    if (i4 >= (N_NODES * H) / 4) return;
    int cbase = (i4 * 4) & (H - 1);
    float4 v = ((float4*)g_x)[i4];
    float y0 = fmaf(v.x, g_scale[cbase + 0], g_shift[cbase + 0]);
    float y1 = fmaf(v.y, g_scale[cbase + 1], g_shift[cbase + 1]);
    float y2 = fmaf(v.z, g_scale[cbase + 2], g_shift[cbase + 2]);
    float y3 = fmaf(v.w, g_scale[cbase + 3], g_shift[cbase + 3]);
    v.x = (y0 > 0.f) ? y0 : expm1f(y0);
    v.y = (y1 > 0.f) ? y1 : expm1f(y1);
    v.z = (y2 > 0.f) ? y2 : expm1f(y2);
    v.w = (y3 > 0.f) ? y3 : expm1f(y3);
    ((float4*)g_x)[i4] = v;
}

// ---------------- head: out = x @ w_head + b_head ----------------
__global__ void k_head(const float* __restrict__ w_head,
                       const float* __restrict__ b_head,
                       float* __restrict__ out) {
    int gwarp = (blockIdx.x * blockDim.x + threadIdx.x) >> 5;
    int lane = threadIdx.x & 31;
    if (gwarp >= N_NODES) return;
    const float* row = g_x + (size_t)gwarp * H;
    float s = 0.f;
    #pragma unroll
    for (int j = 0; j < 8; j++) {
        int ch = lane + 32 * j;
        s = fmaf(row[ch], w_head[ch], s);
    }
    #pragma unroll
    for (int o = 16; o; o >>= 1) s += __shfl_xor_sync(0xffffffffu, s, o);
    if (lane == 0) out[gwarp] = s + b_head[0];
}

// ---------------- launch ----------------
extern "C" void kernel_launch(void* const* d_in, const int* in_sizes, int n_in,
                              void* d_out, int out_size) {
    const float* ctrl   = (const float*)d_in[0];
    const int*   eidx   = (const int*)d_in[1];
    const float* w_in   = (const float*)d_in[2];
    const float* b_in   = (const float*)d_in[3];
    const float* ln_g   = (const float*)d_in[4];
    const float* ln_b   = (const float*)d_in[5];
    const float* W[3]   = { (const float*)d_in[6],  (const float*)d_in[10], (const float*)d_in[14] };
    const float* gam[3] = { (const float*)d_in[8],  (const float*)d_in[12], (const float*)d_in[16] };
    const float* bet[3] = { (const float*)d_in[9],  (const float*)d_in[13], (const float*)d_in[17] };
    const float* w_head = (const float*)d_in[18];
    const float* b_head = (const float*)d_in[19];
    float* out = (float*)d_out;

    const int* src = eidx;
    const int* dst = eidx + E_EDGES;

    // graph structure
    k_zero_deg<<<(N_NODES + 255) / 256, 256>>>();
    k_count<<<E_EDGES / 256, 256>>>(dst);
    k_scan<<<1, 1024>>>();
    k_fill<<<E_EDGES / 256, 256>>>(src, dst);

    // input proj + LN + ELU
    k_input<<<N_NODES / 8, 256>>>(ctrl, w_in, b_in, ln_g, ln_b);

    dim3 gemm_grid(H / BN, (N_NODES + BM - 1) / BM);
    for (int l = 0; l < 3; l++) {
        k_gemm<<<gemm_grid, 256>>>(W[l]);
        k_zero_stats<<<1, H>>>();
        k_aggregate<<<N_NODES / 8, 256>>>();
        k_bn_finalize<<<1, H>>>(gam[l], bet[l]);
        k_apply<<<(N_NODES * H / 4 + 255) / 256, 256>>>();
    }

    k_head<<<N_NODES / 8, 256>>>(w_head, b_head, out);
}

// round 3
// speedup vs baseline: 1.3110x; 1.3110x over previous
#include <cuda_runtime.h>
#include <cuda_bf16.h>
#include <cstdint>
#include <math.h>

#define N_NODES 50000
#define H 256
#define E_EDGES 800000
#define EPS_LN 1e-5f
#define EPS_BN 1e-5f

// ---------------- scratch (device globals; no allocation allowed) -------------
__device__ float g_x[(size_t)N_NODES * H];            // aggregation output (fp32)
__device__ float g_xw[(size_t)N_NODES * H];           // x @ W (fp32, GEMM out)
__device__ __nv_bfloat16 g_xh[(size_t)N_NODES * H];   // activations hi
__device__ __nv_bfloat16 g_xl[(size_t)N_NODES * H];   // activations lo
__device__ __nv_bfloat16 g_wth[3][H * H];             // W^T hi: [n][k]
__device__ __nv_bfloat16 g_wtl[3][H * H];             // W^T lo: [n][k]
__device__ int   g_deg[N_NODES];
__device__ float g_dinv[N_NODES];
__device__ int   g_off[N_NODES + 1];
__device__ int   g_cur[N_NODES];
__device__ int   g_csrc[E_EDGES];
__device__ float g_sum[H];
__device__ float g_sumsq[H];
__device__ float g_scale[H];
__device__ float g_shift[H];

// ---------------- degree / CSR build ----------------
__global__ void k_zero_deg() {
    int i = blockIdx.x * blockDim.x + threadIdx.x;
    if (i < N_NODES) g_deg[i] = 0;
}

__global__ void k_count(const int* __restrict__ dst) {
    int e = blockIdx.x * blockDim.x + threadIdx.x;
    if (e < E_EDGES) atomicAdd(&g_deg[dst[e]], 1);
}

__global__ void k_scan() {
    __shared__ int swarp[32];
    __shared__ int s_carry;
    int tid = threadIdx.x, lane = tid & 31, wid = tid >> 5;
    if (tid == 0) s_carry = 0;
    __syncthreads();
    for (int base = 0; base < N_NODES; base += 1024) {
        int i = base + tid;
        int v = (i < N_NODES) ? g_deg[i] : 0;
        int x = v;
        #pragma unroll
        for (int o = 1; o < 32; o <<= 1) {
            int t = __shfl_up_sync(0xffffffffu, x, o);
            if (lane >= o) x += t;
        }
        if (lane == 31) swarp[wid] = x;
        __syncthreads();
        if (wid == 0) {
            int y = swarp[lane];
            #pragma unroll
            for (int o = 1; o < 32; o <<= 1) {
                int t = __shfl_up_sync(0xffffffffu, y, o);
                if (lane >= o) y += t;
            }
            swarp[lane] = y;
        }
        __syncthreads();
        int incl = x + (wid ? swarp[wid - 1] : 0);
        int carry = s_carry;
        if (i < N_NODES) {
            int o = carry + incl - v;
            g_off[i] = o;
            g_cur[i] = o;
            g_dinv[i] = rsqrtf((float)v + 1.0f);
        }
        __syncthreads();
        if (tid == 1023) s_carry = carry + incl;
        __syncthreads();
    }
    if (threadIdx.x == 0) g_off[N_NODES] = s_carry;
}

__global__ void k_fill(const int* __restrict__ src, const int* __restrict__ dst) {
    int e = blockIdx.x * blockDim.x + threadIdx.x;
    if (e < E_EDGES) {
        int d = dst[e];
        int pos = atomicAdd(&g_cur[d], 1);
        g_csrc[pos] = src[e];
    }
}

// ---------------- W^T split (fp32 -> bf16 hi/lo), [n][k] layout --------------
__global__ void k_wsplit(const float* __restrict__ W,
                         __nv_bfloat16* __restrict__ hi, __nv_bfloat16* __restrict__ lo) {
    int n = blockIdx.x, k = threadIdx.x;
    float w = W[k * H + n];
    __nv_bfloat16 h = __float2bfloat16(w);
    hi[n * H + k] = h;
    lo[n * H + k] = __float2bfloat16(w - __bfloat162float(h));
}

// ---------------- input proj + LayerNorm + ELU -> bf16 hi/lo -----------------
__global__ void k_input(const float* __restrict__ ctrl,
                        const float* __restrict__ w_in, const float* __restrict__ b_in,
                        const float* __restrict__ ln_g, const float* __restrict__ ln_b) {
    int gwarp = (blockIdx.x * blockDim.x + threadIdx.x) >> 5;
    int lane = threadIdx.x & 31;
    if (gwarp >= N_NODES) return;
    float c = ctrl[gwarp];
    float v[8];
    float s = 0.f, s2 = 0.f;
    #pragma unroll
    for (int jp = 0; jp < 4; jp++) {
        int c0 = 2 * (lane + 32 * jp);
        float t0 = fmaf(c, w_in[c0], b_in[c0]);
        float t1 = fmaf(c, w_in[c0 + 1], b_in[c0 + 1]);
        v[2 * jp] = t0; v[2 * jp + 1] = t1;
        s += t0 + t1; s2 += t0 * t0 + t1 * t1;
    }
    #pragma unroll
    for (int o = 16; o; o >>= 1) {
        s  += __shfl_xor_sync(0xffffffffu, s, o);
        s2 += __shfl_xor_sync(0xffffffffu, s2, o);
    }
    float mu = s * (1.0f / H);
    float var = fmaxf(s2 * (1.0f / H) - mu * mu, 0.f);
    float r = rsqrtf(var + EPS_LN);
    __nv_bfloat162* oh = (__nv_bfloat162*)(g_xh + (size_t)gwarp * H);
    __nv_bfloat162* ol = (__nv_bfloat162*)(g_xl + (size_t)gwarp * H);
    #pragma unroll
    for (int jp = 0; jp < 4; jp++) {
        int c0 = 2 * (lane + 32 * jp);
        float y0 = fmaf((v[2 * jp] - mu) * r, ln_g[c0], ln_b[c0]);
        float y1 = fmaf((v[2 * jp + 1] - mu) * r, ln_g[c0 + 1], ln_b[c0 + 1]);
        y0 = (y0 > 0.f) ? y0 : expm1f(y0);
        y1 = (y1 > 0.f) ? y1 : expm1f(y1);
        __nv_bfloat16 h0 = __float2bfloat16(y0), h1 = __float2bfloat16(y1);
        __nv_bfloat16 l0 = __float2bfloat16(y0 - __bfloat162float(h0));
        __nv_bfloat16 l1 = __float2bfloat16(y1 - __bfloat162float(h1));
        oh[lane + 32 * jp] = __nv_bfloat162(h0, h1);
        ol[lane + 32 * jp] = __nv_bfloat162(l0, l1);
    }
}

// ---------------- mma.sync bf16 GEMM: g_xw = (xh+xl) @ (Wh+Wl) ---------------
// CTA tile 128x128, 8 warps (warp tile 32x64), BK=32, K-major padded smem.
#define ASTRIDE 40   // bf16 elems per smem row (80 B: 16B-aligned, conflict-free frags)

__device__ __forceinline__ void mma16816(float* c, const uint32_t* a, const uint32_t* b) {
    asm volatile("mma.sync.aligned.m16n8k16.row.col.f32.bf16.bf16.f32 "
                 "{%0,%1,%2,%3}, {%4,%5,%6,%7}, {%8,%9}, {%0,%1,%2,%3};"
                 : "+f"(c[0]), "+f"(c[1]), "+f"(c[2]), "+f"(c[3])
                 : "r"(a[0]), "r"(a[1]), "r"(a[2]), "r"(a[3]), "r"(b[0]), "r"(b[1]));
}

__global__ __launch_bounds__(256, 2) void k_gemm_mma(const __nv_bfloat16* __restrict__ Bh,
                                                     const __nv_bfloat16* __restrict__ Bl) {
    __shared__ __nv_bfloat16 sAh[128 * ASTRIDE];
    __shared__ __nv_bfloat16 sAl[128 * ASTRIDE];
    __shared__ __nv_bfloat16 sBh[128 * ASTRIDE];
    __shared__ __nv_bfloat16 sBl[128 * ASTRIDE];

    int tid = threadIdx.x, wid = tid >> 5, lane = tid & 31;
    int g = lane >> 2, tg = lane & 3;
    int bm = blockIdx.y * 128, bn = blockIdx.x * 128;
    int wm = (wid & 3) * 32, wn = (wid >> 2) * 64;

    float c[2][8][4] = {};

    int arow = tid >> 1;        // 0..127
    int af4 = (tid & 1) * 2;    // float4 index {0,2}
    int gr = bm + arow;
    bool a_ok = (gr < N_NODES);
    const float4* pAh = (const float4*)(g_xh + (size_t)(a_ok ? gr : 0) * H);
    const float4* pAl = (const float4*)(g_xl + (size_t)(a_ok ? gr : 0) * H);
    const float4* pBh = (const float4*)(Bh + (size_t)(bn + arow) * H);
    const float4* pBl = (const float4*)(Bl + (size_t)(bn + arow) * H);

    for (int kc = 0; kc < 8; kc++) {
        // ---- load tiles: A rows bm..bm+127, B rows bn..bn+127, k cols kc*32..+31
        int ko = kc * 4;  // float4 offset within row (32 bf16 = 4 float4)
        float4 z4 = make_float4(0.f, 0.f, 0.f, 0.f);
        float4 vh0 = a_ok ? pAh[ko + af4]     : z4;
        float4 vh1 = a_ok ? pAh[ko + af4 + 1] : z4;
        float4 vl0 = a_ok ? pAl[ko + af4]     : z4;
        float4 vl1 = a_ok ? pAl[ko + af4 + 1] : z4;
        float4 wh0 = pBh[ko + af4];
        float4 wh1 = pBh[ko + af4 + 1];
        float4 wl0 = pBl[ko + af4];
        float4 wl1 = pBl[ko + af4 + 1];
        int so = arow * ASTRIDE + af4 * 8;   // bf16 index; *2 = byte, 16B aligned
        *(float4*)&sAh[so] = vh0;  *(float4*)&sAh[so + 8] = vh1;
        *(float4*)&sAl[so] = vl0;  *(float4*)&sAl[so + 8] = vl1;
        *(float4*)&sBh[so] = wh0;  *(float4*)&sBh[so + 8] = wh1;
        *(float4*)&sBl[so] = wl0;  *(float4*)&sBl[so + 8] = wl1;
        __syncthreads();

        // ---- compute
        #pragma unroll
        for (int k16 = 0; k16 < 2; k16++) {
            int kb = k16 * 32;  // byte offset of k16 block (16 bf16)
            uint32_t ah[2][4], al[2][4];
            #pragma unroll
            for (int mt = 0; mt < 2; mt++) {
                int r = wm + mt * 16 + g;
                int o = r * (ASTRIDE * 2) + kb + tg * 4;
                ah[mt][0] = *(const uint32_t*)((const char*)sAh + o);
                ah[mt][1] = *(const uint32_t*)((const char*)sAh + o + 8 * ASTRIDE * 2);
                ah[mt][2] = *(const uint32_t*)((const char*)sAh + o + 16);
                ah[mt][3] = *(const uint32_t*)((const char*)sAh + o + 8 * ASTRIDE * 2 + 16);
                al[mt][0] = *(const uint32_t*)((const char*)sAl + o);
                al[mt][1] = *(const uint32_t*)((const char*)sAl + o + 8 * ASTRIDE * 2);
                al[mt][2] = *(const uint32_t*)((const char*)sAl + o + 16);
                al[mt][3] = *(const uint32_t*)((const char*)sAl + o + 8 * ASTRIDE * 2 + 16);
            }
            #pragma unroll
            for (int nt = 0; nt < 8; nt++) {
                int rb = wn + nt * 8 + g;
                int o = rb * (ASTRIDE * 2) + kb + tg * 4;
                uint32_t bh[2], bl[2];
                bh[0] = *(const uint32_t*)((const char*)sBh + o);
                bh[1] = *(const uint32_t*)((const char*)sBh + o + 16);
                bl[0] = *(const uint32_t*)((const char*)sBl + o);
                bl[1] = *(const uint32_t*)((const char*)sBl + o + 16);
                #pragma unroll
                for (int mt = 0; mt < 2; mt++) {
                    mma16816(c[mt][nt], ah[mt], bh);
                    mma16816(c[mt][nt], ah[mt], bl);
                    mma16816(c[mt][nt], al[mt], bh);
                }
            }
        }
        __syncthreads();
    }

    // ---- epilogue
    #pragma unroll
    for (int mt = 0; mt < 2; mt++) {
        int r0 = bm + wm + mt * 16 + g;
        #pragma unroll
        for (int nt = 0; nt < 8; nt++) {
            int col = bn + wn + nt * 8 + tg * 2;
            if (r0 < N_NODES)
                *(float2*)&g_xw[(size_t)r0 * H + col] = make_float2(c[mt][nt][0], c[mt][nt][1]);
            if (r0 + 8 < N_NODES)
                *(float2*)&g_xw[(size_t)(r0 + 8) * H + col] = make_float2(c[mt][nt][2], c[mt][nt][3]);
        }
    }
}

// ---------------- zero BN accumulators ----------------
__global__ void k_zero_stats() {
    int t = threadIdx.x;
    g_sum[t] = 0.f;
    g_sumsq[t] = 0.f;
}

// ---------------- CSR aggregation + fused BN partial stats -------------------
__global__ __launch_bounds__(256) void k_aggregate() {
    __shared__ float s_sum[H];
    __shared__ float s_sq[H];
    int tid = threadIdx.x;
    s_sum[tid] = 0.f;
    s_sq[tid] = 0.f;
    __syncthreads();

    int node = blockIdx.x * 8 + (tid >> 5);
    int lane = tid & 31;

    float dn = g_dinv[node];
    const float4* row = (const float4*)(g_xw + (size_t)node * H);
    float4 a0 = row[lane];
    float4 a1 = row[32 + lane];
    float w = dn * dn;
    float4 acc0 = make_float4(a0.x * w, a0.y * w, a0.z * w, a0.w * w);
    float4 acc1 = make_float4(a1.x * w, a1.y * w, a1.z * w, a1.w * w);

    int beg = g_off[node], end = g_off[node + 1];
    for (int j = beg; j < end; j++) {
        int s = g_csrc[j];
        float coef = g_dinv[s] * dn;
        const float4* r2 = (const float4*)(g_xw + (size_t)s * H);
        float4 b0 = r2[lane];
        float4 b1 = r2[32 + lane];
        acc0.x = fmaf(coef, b0.x, acc0.x);
        acc0.y = fmaf(coef, b0.y, acc0.y);
        acc0.z = fmaf(coef, b0.z, acc0.z);
        acc0.w = fmaf(coef, b0.w, acc0.w);
        acc1.x = fmaf(coef, b1.x, acc1.x);
        acc1.y = fmaf(coef, b1.y, acc1.y);
        acc1.z = fmaf(coef, b1.z, acc1.z);
        acc1.w = fmaf(coef, b1.w, acc1.w);
    }
    float4* out = (float4*)(g_x + (size_t)node * H);
    out[lane] = acc0;
    out[32 + lane] = acc1;

    int c0 = lane * 4, c1 = 128 + lane * 4;
    atomicAdd(&s_sum[c0 + 0], acc0.x); atomicAdd(&s_sq[c0 + 0], acc0.x * acc0.x);
    atomicAdd(&s_sum[c0 + 1], acc0.y); atomicAdd(&s_sq[c0 + 1], acc0.y * acc0.y);
    atomicAdd(&s_sum[c0 + 2], acc0.z); atomicAdd(&s_sq[c0 + 2], acc0.z * acc0.z);
    atomicAdd(&s_sum[c0 + 3], acc0.w); atomicAdd(&s_sq[c0 + 3], acc0.w * acc0.w);
    atomicAdd(&s_sum[c1 + 0], acc1.x); atomicAdd(&s_sq[c1 + 0], acc1.x * acc1.x);
    atomicAdd(&s_sum[c1 + 1], acc1.y); atomicAdd(&s_sq[c1 + 1], acc1.y * acc1.y);
    atomicAdd(&s_sum[c1 + 2], acc1.z); atomicAdd(&s_sq[c1 + 2], acc1.z * acc1.z);
    atomicAdd(&s_sum[c1 + 3], acc1.w); atomicAdd(&s_sq[c1 + 3], acc1.w * acc1.w);

    __syncthreads();
    atomicAdd(&g_sum[tid], s_sum[tid]);
    atomicAdd(&g_sumsq[tid], s_sq[tid]);
}

// ---------------- BN finalize ----------------
__global__ void k_bn_finalize(const float* __restrict__ gamma,
                              const float* __restrict__ beta) {
    int t = threadIdx.x;
    float mean = g_sum[t] * (1.0f / N_NODES);
    float var = fmaxf(g_sumsq[t] * (1.0f / N_NODES) - mean * mean, 0.f);
    float r = rsqrtf(var + EPS_BN);
    float sc = r * gamma[t];
    g_scale[t] = sc;
    g_shift[t] = beta[t] - mean * sc;
}

// ---------------- BN apply + ELU -> bf16 hi/lo ----------------
__global__ void k_apply() {
    int i4 = blockIdx.x * blockDim.x + threadIdx.x;   // float4 index
    if (i4 >= (N_NODES * H) / 4) return;
    int cbase = (i4 * 4) & (H - 1);
    float4 v = ((const float4*)g_x)[i4];
    float y0 = fmaf(v.x, g_scale[cbase + 0], g_shift[cbase + 0]);
    float y1 = fmaf(v.y, g_scale[cbase + 1], g_shift[cbase + 1]);
    float y2 = fmaf(v.z, g_scale[cbase + 2], g_shift[cbase + 2]);
    float y3 = fmaf(v.w, g_scale[cbase + 3], g_shift[cbase + 3]);
    y0 = (y0 > 0.f) ? y0 : expm1f(y0);
    y1 = (y1 > 0.f) ? y1 : expm1f(y1);
    y2 = (y2 > 0.f) ? y2 : expm1f(y2);
    y3 = (y3 > 0.f) ? y3 : expm1f(y3);
    __nv_bfloat16 h0 = __float2bfloat16(y0), h1 = __float2bfloat16(y1);
    __nv_bfloat16 h2 = __float2bfloat16(y2), h3 = __float2bfloat16(y3);
    __nv_bfloat16 l0 = __float2bfloat16(y0 - __bfloat162float(h0));
    __nv_bfloat16 l1 = __float2bfloat16(y1 - __bfloat162float(h1));
    __nv_bfloat16 l2 = __float2bfloat16(y2 - __bfloat162float(h2));
    __nv_bfloat16 l3 = __float2bfloat16(y3 - __bfloat162float(h3));
    __nv_bfloat162* oh = (__nv_bfloat162*)g_xh;
    __nv_bfloat162* ol = (__nv_bfloat162*)g_xl;
    oh[2 * i4 + 0] = __nv_bfloat162(h0, h1);
    oh[2 * i4 + 1] = __nv_bfloat162(h2, h3);
    ol[2 * i4 + 0] = __nv_bfloat162(l0, l1);
    ol[2 * i4 + 1] = __nv_bfloat162(l2, l3);
}

// ---------------- head ----------------
__global__ void k_head(const float* __restrict__ w_head,
                       const float* __restrict__ b_head,
                       float* __restrict__ out) {
    int gwarp = (blockIdx.x * blockDim.x + threadIdx.x) >> 5;
    int lane = threadIdx.x & 31;
    if (gwarp >= N_NODES) return;
    const __nv_bfloat16* rh = g_xh + (size_t)gwarp * H;
    const __nv_bfloat16* rl = g_xl + (size_t)gwarp * H;
    float s = 0.f;
    #pragma unroll
    for (int j = 0; j < 8; j++) {
        int ch = lane + 32 * j;
        float x = __bfloat162float(rh[ch]) + __bfloat162float(rl[ch]);
        s = fmaf(x, w_head[ch], s);
    }
    #pragma unroll
    for (int o = 16; o; o >>= 1) s += __shfl_xor_sync(0xffffffffu, s, o);
    if (lane == 0) out[gwarp] = s + b_head[0];
}

// ---------------- launch ----------------
extern "C" void kernel_launch(void* const* d_in, const int* in_sizes, int n_in,
                              void* d_out, int out_size) {
    const float* ctrl   = (const float*)d_in[0];
    const int*   eidx   = (const int*)d_in[1];
    const float* w_in   = (const float*)d_in[2];
    const float* b_in   = (const float*)d_in[3];
    const float* ln_g   = (const float*)d_in[4];
    const float* ln_b   = (const float*)d_in[5];
    const float* W[3]   = { (const float*)d_in[6],  (const float*)d_in[10], (const float*)d_in[14] };
    const float* gam[3] = { (const float*)d_in[8],  (const float*)d_in[12], (const float*)d_in[16] };
    const float* bet[3] = { (const float*)d_in[9],  (const float*)d_in[13], (const float*)d_in[17] };
    const float* w_head = (const float*)d_in[18];
    const float* b_head = (const float*)d_in[19];
    float* out = (float*)d_out;

    const int* src = eidx;
    const int* dst = eidx + E_EDGES;

    // graph structure
    k_zero_deg<<<(N_NODES + 255) / 256, 256>>>();
    k_count<<<E_EDGES / 256, 256>>>(dst);
    k_scan<<<1, 1024>>>();
    k_fill<<<E_EDGES / 256, 256>>>(src, dst);

    // weight split (W^T -> bf16 hi/lo)
    __nv_bfloat16* wh;  __nv_bfloat16* wl;
    cudaGetSymbolAddress((void**)&wh, g_wth);
    cudaGetSymbolAddress((void**)&wl, g_wtl);
    for (int l = 0; l < 3; l++)
        k_wsplit<<<H, H>>>(W[l], wh + (size_t)l * H * H, wl + (size_t)l * H * H);

    // input proj + LN + ELU
    k_input<<<N_NODES / 8, 256>>>(ctrl, w_in, b_in, ln_g, ln_b);

    dim3 gemm_grid(H / 128, (N_NODES + 127) / 128);
    for (int l = 0; l < 3; l++) {
        k_gemm_mma<<<gemm_grid, 256>>>(wh + (size_t)l * H * H, wl + (size_t)l * H * H);
        k_zero_stats<<<1, H>>>();
        k_aggregate<<<N_NODES / 8, 256>>>();
        k_bn_finalize<<<1, H>>>(gam[l], bet[l]);
        k_apply<<<(N_NODES * H / 4 + 255) / 256, 256>>>();
    }

    k_head<<<N_NODES / 8, 256>>>(w_head, b_head, out);
}